// round 4
// baseline (speedup 1.0000x reference)
#include <cuda_runtime.h>
#include <math.h>

#define BB 64
#define RR 28
#define SS 784       // RR*RR
#define CC 256
#define HH 8
#define DR 98        // SS/HH
#define EE 128

typedef unsigned long long u64;

// ---------- packed f32x2 helpers (Blackwell FFMA2 path) ----------
__device__ __forceinline__ u64 pk2(float lo, float hi) {
    u64 r; asm("mov.b64 %0, {%1, %2};" : "=l"(r) : "f"(lo), "f"(hi)); return r;
}
__device__ __forceinline__ float2 upk(u64 v) {
    float2 f; asm("mov.b64 {%0, %1}, %2;" : "=f"(f.x), "=f"(f.y) : "l"(v)); return f;
}
__device__ __forceinline__ void fma2(u64& d, u64 a, u64 b) {
    asm("fma.rn.f32x2 %0, %1, %2, %0;" : "+l"(d) : "l"(a), "l"(b));
}

// ---------- scratch (no allocation allowed -> device globals) ----------
__device__ __align__(16) float g_qT[BB * CC * SS];        // avg-pooled x, [b][c][s]
__device__ __align__(16) float g_kT[BB * CC * SS];        // max-pooled x, [b][c][s]
__device__ __align__(16) float g_vpre[BB * SS * CC];      // conv out,     [b][s][c]
__device__ __align__(16) float g_vT[BB * CC * SS];        // avg-pooled v, [b][c][s]
__device__ __align__(16) float g_qp[BB * HH * CC * EE];   // q proj [bh][c][e]
__device__ __align__(16) float g_kp[BB * HH * CC * EE];   // k proj [bh][c][e]
__device__ __align__(16) float g_scores[(size_t)BB * HH * CC * CC]; // [bh][c][f]
__device__ __align__(16) float g_idenom[BB * HH * CC];    // 1/denom per [bh][c]

// =====================================================================
// Kernel 1: 3x3 SAME conv (NHWC, HWIO) + bias -> g_vpre
// One block per (b,y) image row. smem: padded 3-row slab [3][30][256].
// Thread = (oc pair, pixel half). Inner loop: FMA2-bound, weight
// prefetch one ic ahead to hide L2 latency; 2 blocks/SM for latency hiding.
// =====================================================================
__global__ void __launch_bounds__(256, 2) conv_kernel(const float* __restrict__ x,
                                                      const float* __restrict__ w,
                                                      const float* __restrict__ bias) {
    extern __shared__ float smem[];
    float* xs = smem; // [3][30][256], col 0 and 29 are zero pads
    const int bid = blockIdx.x;
    const int b = bid / RR, y = bid % RR;
    const int tid = threadIdx.x;

    for (int ky = 0; ky < 3; ky++) {
        float* xr = xs + ky * 30 * CC;
        const int yy = y + ky - 1;
        if (tid < 64)       ((float4*)xr)[tid] = make_float4(0.f, 0.f, 0.f, 0.f);
        else if (tid < 128) ((float4*)(xr + 29 * CC))[tid - 64] = make_float4(0.f, 0.f, 0.f, 0.f);
        float4* d4 = (float4*)(xr + CC);
        if (yy >= 0 && yy < RR) {
            const float4* s4 = (const float4*)(x + ((size_t)(b * RR + yy) * RR) * CC);
            for (int i = tid; i < RR * CC / 4; i += 256) d4[i] = s4[i];
        } else {
            const float4 z = make_float4(0.f, 0.f, 0.f, 0.f);
            for (int i = tid; i < RR * CC / 4; i += 256) d4[i] = z;
        }
    }
    __syncthreads();

    const int ocp = tid & 127, ph = tid >> 7;
    const int oc0 = ocp * 2, pb = ph * 14;

    u64 acc[14];
    {
        u64 binit = pk2(bias[oc0], bias[oc0 + 1]);
#pragma unroll
        for (int p = 0; p < 14; p++) acc[p] = binit;
    }

#pragma unroll
    for (int ky = 0; ky < 3; ky++) {
        const float* xr = xs + ky * 30 * CC + pb * CC;
        const float* wr = w + (size_t)ky * 3 * CC * CC + oc0;

        // prefetch weights for ic=0
        u64 w2cur[3];
#pragma unroll
        for (int kx = 0; kx < 3; kx++) {
            const float2 wf = __ldg((const float2*)(wr + (size_t)kx * CC * CC));
            w2cur[kx] = pk2(wf.x, wf.y);
        }

#pragma unroll 1
        for (int ic = 0; ic < CC; ic++) {
            // prefetch next ic's weights (clamped; last iter re-reads ic=255 harmlessly)
            const int icn = (ic < CC - 1) ? ic + 1 : ic;
            u64 w2nxt[3];
#pragma unroll
            for (int kx = 0; kx < 3; kx++) {
                const float2 wf = __ldg((const float2*)(wr + ((size_t)kx * CC + icn) * CC));
                w2nxt[kx] = pk2(wf.x, wf.y);
            }

            u64 xv[16];
#pragma unroll
            for (int t = 0; t < 16; t++) { float v = xr[t * CC + ic]; xv[t] = pk2(v, v); }
#pragma unroll
            for (int kx = 0; kx < 3; kx++) {
#pragma unroll
                for (int p = 0; p < 14; p++) fma2(acc[p], xv[p + kx], w2cur[kx]);
            }
#pragma unroll
            for (int kx = 0; kx < 3; kx++) w2cur[kx] = w2nxt[kx];
        }
    }

    float* dst = g_vpre + ((size_t)(b * SS + y * RR + pb)) * CC + oc0;
#pragma unroll
    for (int p = 0; p < 14; p++) {
        *(float2*)(dst + (size_t)p * CC) = upk(acc[p]);
    }
}

// =====================================================================
// Kernel 2: 3x3 SAME pools (valid-count avg, max) with transpose to [b][c][s]
// MODE 0: src=x -> g_qT (avg) + g_kT (max).  MODE 1: src=g_vpre -> g_vT (avg)
// =====================================================================
template <int MODE>
__global__ void __launch_bounds__(256) pool_kernel(const float* __restrict__ xin) {
    extern __shared__ float smem[];
    float* xs = smem;               // [3][28][256]
    float* oA = xs + 3 * RR * CC;   // [28][257]
    float* oM = oA + RR * 257;      // [28][257]
    const int bid = blockIdx.x;
    const int b = bid / RR, y = bid % RR;
    const int tid = threadIdx.x;
    const float* src = (MODE == 0) ? xin : g_vpre;

    const int dy0 = (y == 0) ? 0 : -1;
    const int dy1 = (y == RR - 1) ? 0 : 1;
    for (int dy = dy0; dy <= dy1; dy++) {
        const float4* s4 = (const float4*)(src + ((size_t)(b * RR + y + dy) * RR) * CC);
        float4* d4 = (float4*)(xs + (dy + 1) * RR * CC);
        for (int i = tid; i < RR * CC / 4; i += 256) d4[i] = s4[i];
    }
    __syncthreads();

    const int c = tid;
    const int rcnt = dy1 - dy0 + 1;
    for (int px = 0; px < RR; px++) {
        const int x0 = (px > 0) ? px - 1 : 0;
        const int x1 = (px < RR - 1) ? px + 1 : RR - 1;
        float s = 0.f, m = -3.4e38f;
        for (int dy = dy0; dy <= dy1; dy++) {
            const float* row = xs + (dy + 1) * RR * CC;
            for (int xx = x0; xx <= x1; xx++) {
                const float v = row[xx * CC + c];
                s += v;
                if (MODE == 0) m = fmaxf(m, v);
            }
        }
        const float cnt = (float)(rcnt * (x1 - x0 + 1));
        oA[px * 257 + c] = s / cnt;
        if (MODE == 0) oM[px * 257 + c] = m;
    }
    __syncthreads();

    float* dstA = (MODE == 0) ? g_qT : g_vT;
    for (int i = tid; i < RR * CC; i += 256) {
        const int cc = i / RR, px = i % RR;
        const size_t o = ((size_t)(b * CC + cc)) * SS + y * RR + px;
        dstA[o] = oA[px * 257 + cc];
        if (MODE == 0) g_kT[o] = oM[px * 257 + cc];
    }
}

// =====================================================================
// Kernel 3: per-head QK projection. For (b,h): [64x98] @ [98x128] + bias.
// grid (4 row-tiles, 512 bh, 2 {q,k}); 256 thr; each thread 4x4 f32x2 tile.
// =====================================================================
__global__ void __launch_bounds__(256, 2) proj_kernel(const float* __restrict__ wqk,
                                                      const float* __restrict__ wqkb) {
    extern __shared__ float smem[];
    float2* Ws = (float2*)smem;        // [98][64] e-pairs
    float* As = smem + DR * EE;        // [64][98]
    const int cb = blockIdx.x * 64;
    const int bh = blockIdx.y;
    const int b = bh >> 3, h = bh & 7;
    const int tid = threadIdx.x;
    const float* srcT = blockIdx.z ? g_kT : g_qT;
    float* dst = blockIdx.z ? g_kp : g_qp;

    const float2* wsrc = (const float2*)(wqk + (size_t)h * DR * EE);
    for (int i = tid; i < DR * EE / 2; i += 256) Ws[i] = wsrc[i];
    for (int i = tid; i < 64 * DR; i += 256) {
        const int r = i / DR, d = i - r * DR;
        As[r * DR + d] = srcT[((size_t)(b * CC + cb + r)) * SS + h * DR + d];
    }
    __syncthreads();

    const int tx = tid & 15, ty = tid >> 4;
    u64 acc[4][4];
#pragma unroll
    for (int j = 0; j < 4; j++) {
        const float2 b2 = *(const float2*)(wqkb + h * EE + 2 * (tx + 16 * j));
        const u64 bi = pk2(b2.x, b2.y);
#pragma unroll
        for (int i = 0; i < 4; i++) acc[i][j] = bi;
    }
    for (int k = 0; k < DR; k++) {
        u64 a[4], bw[4];
#pragma unroll
        for (int i = 0; i < 4; i++) { float v = As[(ty + 16 * i) * DR + k]; a[i] = pk2(v, v); }
#pragma unroll
        for (int j = 0; j < 4; j++) bw[j] = *(const u64*)&Ws[k * 64 + tx + 16 * j];
#pragma unroll
        for (int i = 0; i < 4; i++)
#pragma unroll
            for (int j = 0; j < 4; j++) fma2(acc[i][j], a[i], bw[j]);
    }
#pragma unroll
    for (int i = 0; i < 4; i++) {
        float* drow = dst + ((size_t)bh * CC + cb + ty + 16 * i) * EE;
#pragma unroll
        for (int j = 0; j < 4; j++) *(float2*)(drow + 2 * (tx + 16 * j)) = upk(acc[i][j]);
    }
}

// =====================================================================
// Kernel 4: scores = q @ k^T over E=128 (f32x2 over e-pairs, hi+lo fold)
// grid (4 c-tiles, 4 f-tiles, 512 bh); 64x64 out per block.
// =====================================================================
__global__ void __launch_bounds__(256, 3) scores_kernel() {
    extern __shared__ float smem[];
    float2* qs = (float2*)smem;      // [64][65]
    float2* ks = qs + 64 * 65;       // [64][65]
    const int cb = blockIdx.x * 64, fb = blockIdx.y * 64;
    const int bh = blockIdx.z;
    const int tid = threadIdx.x;

    const float2* q2 = (const float2*)(g_qp + ((size_t)bh * CC) * EE);
    const float2* k2 = (const float2*)(g_kp + ((size_t)bh * CC) * EE);
    for (int i = tid; i < 64 * 64; i += 256) {
        const int r = i >> 6, e = i & 63;
        qs[r * 65 + e] = q2[(size_t)(cb + r) * 64 + e];
        ks[r * 65 + e] = k2[(size_t)(fb + r) * 64 + e];
    }
    __syncthreads();

    const int tx = tid & 15, ty = tid >> 4;
    u64 acc[4][4];
#pragma unroll
    for (int i = 0; i < 4; i++)
#pragma unroll
        for (int j = 0; j < 4; j++) acc[i][j] = 0ull;

    for (int e = 0; e < 64; e++) {
        u64 a[4], kk[4];
#pragma unroll
        for (int i = 0; i < 4; i++) a[i] = *(const u64*)&qs[(ty + 16 * i) * 65 + e];
#pragma unroll
        for (int j = 0; j < 4; j++) kk[j] = *(const u64*)&ks[(tx + 16 * j) * 65 + e];
#pragma unroll
        for (int i = 0; i < 4; i++)
#pragma unroll
            for (int j = 0; j < 4; j++) fma2(acc[i][j], a[i], kk[j]);
    }
    float* outp = g_scores + ((size_t)bh * CC + cb) * CC + fb;
#pragma unroll
    for (int i = 0; i < 4; i++)
#pragma unroll
        for (int j = 0; j < 4; j++) {
            const float2 v = upk(acc[i][j]);
            outp[(size_t)(ty + 16 * i) * CC + tx + 16 * j] = v.x + v.y;
        }
}

// =====================================================================
// Kernel 5: content temperature. rowmean over f, matvec through wp_w,
// sigmoid, idenom = 128^-(0.2+s) = 2^(-7*(0.2+s)).  One block per bh.
// =====================================================================
__global__ void __launch_bounds__(256) temp_kernel(const float* __restrict__ wp,
                                                   const float* __restrict__ wpb) {
    __shared__ float smean[CC];
    const int bh = blockIdx.x;
    const int tid = threadIdx.x, lane = tid & 31, warp = tid >> 5;

    for (int k = 0; k < 32; k++) {
        const int r = warp + 8 * k;
        const float* row = g_scores + ((size_t)bh * CC + r) * CC;
        float s = 0.f;
#pragma unroll
        for (int j = 0; j < 8; j++) s += row[lane + 32 * j];
#pragma unroll
        for (int o = 16; o; o >>= 1) s += __shfl_xor_sync(0xffffffffu, s, o);
        if (lane == 0) smean[r] = s * (1.f / (float)CC);
    }
    __syncthreads();

    float a = wpb[tid];
    for (int c = 0; c < CC; c++) a = fmaf(smean[c], wp[c * CC + tid], a);
    const float sp = 1.f / (1.f + __expf(-a));
    g_idenom[bh * CC + tid] = exp2f(-7.f * (0.2f + sp));
}

// =====================================================================
// Kernel 6: softmax(scores * idenom) @ v, residual add, write output.
// grid (4 c-tiles, 512 bh); softmax in smem, f32x2 GEMM over f-pairs,
// smem-transposed epilogue for coalesced NHWC stores.
// =====================================================================
__global__ void __launch_bounds__(256, 2) att_kernel(const float* __restrict__ x,
                                                     float* __restrict__ out) {
    extern __shared__ float smem[];
    float* ss = smem;               // [64][258] scores tile -> exp values
    float* vsf = ss + 64 * 258;     // [98][66] v chunk; reused as att [64][100]
    __shared__ float rs[64];
    const int cb = blockIdx.x * 64;
    const int bh = blockIdx.y;
    const int b = bh >> 3, h = bh & 7;
    const int tid = threadIdx.x, lane = tid & 31, warp = tid >> 5;

    for (int i = tid; i < 64 * 256; i += 256) {
        const int r = i >> 8, f = i & 255;
        ss[r * 258 + f] = g_scores[((size_t)bh * CC + cb + r) * CC + f];
    }
    __syncthreads();

    // softmax per row (8 warps x 8 rounds = 64 rows), scale by idenom
    for (int k = 0; k < 8; k++) {
        const int r = warp + 8 * k;
        const float id = g_idenom[bh * CC + cb + r];
        float* row = ss + r * 258;
        float m = -3.4e38f;
#pragma unroll
        for (int j = 0; j < 8; j++) m = fmaxf(m, row[lane + 32 * j]);
#pragma unroll
        for (int o = 16; o; o >>= 1) m = fmaxf(m, __shfl_xor_sync(0xffffffffu, m, o));
        float sum = 0.f;
#pragma unroll
        for (int j = 0; j < 8; j++) {
            const float e = __expf((row[lane + 32 * j] - m) * id);
            row[lane + 32 * j] = e;
            sum += e;
        }
#pragma unroll
        for (int o = 16; o; o >>= 1) sum += __shfl_xor_sync(0xffffffffu, sum, o);
        if (lane == 0) rs[r] = 1.f / sum;
    }

    // GEMM: [64 c x 256 f] @ [256 f x 98 d], f chunked by 64
    const int c = tid & 63, dg = tid >> 6;
    u64 acc[25];
#pragma unroll
    for (int k = 0; k < 25; k++) acc[k] = 0ull;

    for (int fc = 0; fc < 4; fc++) {
        __syncthreads();
        for (int i = tid; i < 64 * DR; i += 256) {
            const int f = i / DR, d = i - f * DR;
            vsf[d * 66 + f] = g_vT[((size_t)(b * CC + fc * 64 + f)) * SS + h * DR + d];
        }
        __syncthreads();
        for (int fp = 0; fp < 32; fp++) {
            const u64 sv = *(const u64*)&ss[c * 258 + fc * 64 + 2 * fp];
#pragma unroll
            for (int k = 0; k < 25; k++) {
                const int d = dg + 4 * k;
                if (d < DR) fma2(acc[k], sv, *(const u64*)&vsf[d * 66 + 2 * fp]);
            }
        }
    }

    __syncthreads();
    float* as = vsf; // reuse as att stage [64][100]
#pragma unroll
    for (int k = 0; k < 25; k++) {
        const int d = dg + 4 * k;
        if (d < DR) {
            const float2 v = upk(acc[k]);
            as[c * 100 + d] = (v.x + v.y) * rs[c];
        }
    }
    __syncthreads();

    for (int i = tid; i < DR * 64; i += 256) {
        const int d = i >> 6, cc = i & 63;
        const size_t o = ((size_t)b * SS + h * DR + d) * CC + cb + cc;
        out[o] = x[o] + as[cc * 100 + d];
    }
}

// =====================================================================
extern "C" void kernel_launch(void* const* d_in, const int* in_sizes, int n_in,
                              void* d_out, int out_size) {
    const float* x    = (const float*)d_in[0];
    const float* wqkw = (const float*)d_in[1];
    const float* wqkb = (const float*)d_in[2];
    const float* wpw  = (const float*)d_in[3];
    const float* wpb  = (const float*)d_in[4];
    const float* wvw  = (const float*)d_in[5];
    const float* wvb  = (const float*)d_in[6];
    float* out = (float*)d_out;
    (void)in_sizes; (void)n_in; (void)out_size;

    const int conv_smem  = 3 * 30 * CC * 4;                       // 92160
    const int pool_smem  = (3 * RR * CC + 2 * RR * 257) * 4;      // 143584
    const int proj_smem  = (DR * EE + 64 * DR) * 4;               // 75264
    const int sc_smem    = 2 * 64 * 65 * 8;                       // 66560
    const int att_smem   = (64 * 258 + DR * 66) * 4;              // 91920

    cudaFuncSetAttribute(conv_kernel,   cudaFuncAttributeMaxDynamicSharedMemorySize, conv_smem);
    cudaFuncSetAttribute(pool_kernel<0>, cudaFuncAttributeMaxDynamicSharedMemorySize, pool_smem);
    cudaFuncSetAttribute(pool_kernel<1>, cudaFuncAttributeMaxDynamicSharedMemorySize, pool_smem);
    cudaFuncSetAttribute(proj_kernel,   cudaFuncAttributeMaxDynamicSharedMemorySize, proj_smem);
    cudaFuncSetAttribute(scores_kernel, cudaFuncAttributeMaxDynamicSharedMemorySize, sc_smem);
    cudaFuncSetAttribute(att_kernel,    cudaFuncAttributeMaxDynamicSharedMemorySize, att_smem);

    conv_kernel<<<BB * RR, 256, conv_smem>>>(x, wvw, wvb);   // x -> g_vpre
    pool_kernel<0><<<BB * RR, 256, pool_smem>>>(x);          // x -> g_qT (avg), g_kT (max)
    pool_kernel<1><<<BB * RR, 256, pool_smem>>>(x);          // g_vpre -> g_vT (avg)

    dim3 pg(4, BB * HH, 2);
    proj_kernel<<<pg, 256, proj_smem>>>(wqkw, wqkb);         // -> g_qp, g_kp

    dim3 sg(4, 4, BB * HH);
    scores_kernel<<<sg, 256, sc_smem>>>();                   // -> g_scores

    temp_kernel<<<BB * HH, 256>>>(wpw, wpb);                 // -> g_idenom

    dim3 ag(4, BB * HH);
    att_kernel<<<ag, 256, att_smem>>>(x, out);               // -> d_out
}

// round 12
// speedup vs baseline: 1.3188x; 1.3188x over previous
#include <cuda_runtime.h>
#include <cuda_bf16.h>
#include <mma.h>
#include <math.h>
#include <cstdint>

using namespace nvcuda;

#define BB 64
#define RR 28
#define SS 784       // RR*RR
#define CC 256
#define HH 8
#define DR 98        // SS/HH
#define EE 128

typedef unsigned long long u64;

// ---------- packed f32x2 helpers (Blackwell FFMA2 path) ----------
__device__ __forceinline__ u64 pk2(float lo, float hi) {
    u64 r; asm("mov.b64 %0, {%1, %2};" : "=l"(r) : "f"(lo), "f"(hi)); return r;
}
__device__ __forceinline__ float2 upk(u64 v) {
    float2 f; asm("mov.b64 {%0, %1}, %2;" : "=f"(f.x), "=f"(f.y) : "l"(v)); return f;
}
__device__ __forceinline__ void fma2(u64& d, u64 a, u64 b) {
    asm("fma.rn.f32x2 %0, %1, %2, %0;" : "+l"(d) : "l"(a), "l"(b));
}

// ---------- scratch (no allocation allowed -> device globals) ----------
__device__ __align__(16) float g_qT[BB * CC * SS];        // avg-pooled x, [b][c][s]
__device__ __align__(16) float g_kT[BB * CC * SS];        // max-pooled x, [b][c][s]
__device__ __align__(16) float g_vpre[BB * SS * CC];      // conv out (no bias), [b][s][c]
__device__ __align__(16) float g_vT[BB * CC * SS];        // avg-pooled v + bias, [b][c][s]
__device__ __align__(16) float g_qp[BB * HH * CC * EE];   // q proj [bh][c][e]
__device__ __align__(16) float g_kp[BB * HH * CC * EE];   // k proj [bh][c][e]
__device__ __align__(16) float g_scores[(size_t)BB * HH * CC * CC]; // [bh][c][f]
__device__ __align__(16) float g_idenom[BB * HH * CC];    // 1/denom per [bh][c]
// bf16 hi/lo splits for tensor-core conv
__device__ __align__(16) __nv_bfloat16 g_xhi[BB * SS * CC];
__device__ __align__(16) __nv_bfloat16 g_xlo[BB * SS * CC];
__device__ __align__(16) __nv_bfloat16 g_whi[36 * 256 * 64];  // [chunk][oc][k]
__device__ __align__(16) __nv_bfloat16 g_wlo[36 * 256 * 64];

// =====================================================================
// Prep 1: x -> bf16 hi/lo split
// =====================================================================
__global__ void __launch_bounds__(256) xsplit_kernel(const float* __restrict__ x) {
    const int i = blockIdx.x * 256 + threadIdx.x;
    if (i >= BB * SS * CC) return;
    const float v = x[i];
    const __nv_bfloat16 hi = __float2bfloat16(v);
    g_xhi[i] = hi;
    g_xlo[i] = __float2bfloat16(v - __bfloat162float(hi));
}

// =====================================================================
// Prep 2: w [ky][kx][ic][oc] -> bf16 hi/lo, transposed to [chunk][oc][k64]
// chunk = tap*4 + icq.
// =====================================================================
__global__ void __launch_bounds__(256) wsplit_kernel(const float* __restrict__ w) {
    const int i = blockIdx.x * 256 + threadIdx.x;
    if (i >= 36 * 256 * 64) return;
    const int c = i >> 14;              // /16384
    const int r = i & 16383;
    const int n = r >> 6, j = r & 63;   // n = oc, j = ic_local
    const int tap = c >> 2, icq = c & 3;
    const float v = w[((size_t)(tap * 256 + icq * 64 + j)) * 256 + n];
    const __nv_bfloat16 hi = __float2bfloat16(v);
    g_whi[i] = hi;
    g_wlo[i] = __float2bfloat16(v - __bfloat162float(hi));
}

// =====================================================================
// Kernel 1: 3x3 SAME conv via WMMA (HMMA) implicit GEMM, bf16 hi/lo 3-pass.
// CTA = 128 px x 128 oc (grid 392 x 2); 8 warps, each a 32x64 tile
// (2x4 wmma 16x16x16 frags). K = 2304 in 36 chunks of 64.
// smem ld=72 bf16 -> ldmatrix bank-conflict-free. No bias here (folded
// into pool<1>, exact for spatially-constant bias under valid-count avg).
// =====================================================================
#define CAW 72
__global__ void __launch_bounds__(256, 2) wconv_kernel() {
    extern __shared__ __nv_bfloat16 smw[];
    __nv_bfloat16* Ah = smw;                  // [128][72]
    __nv_bfloat16* Al = Ah + 128 * CAW;
    __nv_bfloat16* Bh = Al + 128 * CAW;       // [128 oc][72]
    __nv_bfloat16* Bl = Bh + 128 * CAW;
    const int tile = blockIdx.x;              // 0..391  (128-px tiles)
    const int ocb  = blockIdx.y * 128;        // 0 or 128
    const int tid = threadIdx.x;
    const int wid = tid >> 5;
    const int wm = wid & 3, wn = wid >> 2;    // wm: 32-px band, wn: 64-oc band

    wmma::fragment<wmma::accumulator, 16, 16, 16, float> acc[2][4];
#pragma unroll
    for (int i = 0; i < 2; i++)
#pragma unroll
        for (int j = 0; j < 4; j++) wmma::fill_fragment(acc[i][j], 0.0f);

    const int jp = tid & 31;       // A-fill: ic-pair column
    const int row0 = tid >> 5;     // A-fill: rows row0 + 8k

    for (int cidx = 0; cidx < 36; cidx++) {
        const int tap = cidx >> 2, icq = cidx & 3;
        const int ky = tap / 3, kx = tap % 3;
        __syncthreads();
        // ---- A fill: im2col patch (hi+lo), u32 = 2 bf16 ----
        {
            uint32_t* ah = (uint32_t*)Ah;
            uint32_t* al = (uint32_t*)Al;
            const int icb = icq * 64 + 2 * jp;
#pragma unroll
            for (int k = 0; k < 16; k++) {
                const int row = row0 + (k << 3);
                const int gp = tile * 128 + row;
                const int b = gp / SS, pp = gp % SS;
                const int y = pp / RR, x0 = pp % RR;
                const int yy = y + ky - 1, xx = x0 + kx - 1;
                uint32_t vh = 0u, vl = 0u;
                if (yy >= 0 && yy < RR && xx >= 0 && xx < RR) {
                    const size_t o = ((size_t)(b * SS + yy * RR + xx)) * CC + icb;
                    vh = *(const uint32_t*)(g_xhi + o);
                    vl = *(const uint32_t*)(g_xlo + o);
                }
                ah[row * 36 + jp] = vh;
                al[row * 36 + jp] = vl;
            }
        }
        // ---- B fill: weights [oc][64] -> smem [oc][72] ----
        {
            uint32_t* bh = (uint32_t*)Bh;
            uint32_t* bl = (uint32_t*)Bl;
            const uint32_t* sh = (const uint32_t*)(g_whi + ((size_t)cidx * 256 + ocb) * 64);
            const uint32_t* sl = (const uint32_t*)(g_wlo + ((size_t)cidx * 256 + ocb) * 64);
            for (int i = tid; i < 128 * 32; i += 256) {
                const int oc = i >> 5, j = i & 31;
                bh[oc * 36 + j] = sh[i];
                bl[oc * 36 + j] = sl[i];
            }
        }
        __syncthreads();
        // ---- compute: 4 k16 steps, 3 passes (hi*hi, lo*hi, hi*lo) ----
#pragma unroll
        for (int ks = 0; ks < 4; ks++) {
            wmma::fragment<wmma::matrix_a, 16, 16, 16, __nv_bfloat16, wmma::row_major> a_hi[2], a_lo[2];
#pragma unroll
            for (int mf = 0; mf < 2; mf++) {
                wmma::load_matrix_sync(a_hi[mf], Ah + (wm * 32 + mf * 16) * CAW + ks * 16, CAW);
                wmma::load_matrix_sync(a_lo[mf], Al + (wm * 32 + mf * 16) * CAW + ks * 16, CAW);
            }
#pragma unroll
            for (int nf = 0; nf < 4; nf++) {
                wmma::fragment<wmma::matrix_b, 16, 16, 16, __nv_bfloat16, wmma::col_major> b_hi, b_lo;
                wmma::load_matrix_sync(b_hi, Bh + (wn * 64 + nf * 16) * CAW + ks * 16, CAW);
                wmma::load_matrix_sync(b_lo, Bl + (wn * 64 + nf * 16) * CAW + ks * 16, CAW);
#pragma unroll
                for (int mf = 0; mf < 2; mf++) {
                    wmma::mma_sync(acc[mf][nf], a_hi[mf], b_hi, acc[mf][nf]);
                    wmma::mma_sync(acc[mf][nf], a_lo[mf], b_hi, acc[mf][nf]);
                    wmma::mma_sync(acc[mf][nf], a_hi[mf], b_lo, acc[mf][nf]);
                }
            }
        }
    }
    // ---- store straight to global (bias added later in pool<1>) ----
#pragma unroll
    for (int mf = 0; mf < 2; mf++)
#pragma unroll
        for (int nf = 0; nf < 4; nf++) {
            float* dst = g_vpre + ((size_t)(tile * 128 + wm * 32 + mf * 16)) * CC
                       + ocb + wn * 64 + nf * 16;
            wmma::store_matrix_sync(dst, acc[mf][nf], CC, wmma::mem_row_major);
        }
}
#define WCONV_SMEM (4 * 128 * CAW * 2)   // 73728 B

// =====================================================================
// Kernel 2: 3x3 SAME pools (valid-count avg, max) with transpose to [b][c][s]
// MODE 0: src=x -> g_qT (avg) + g_kT (max).  MODE 1: src=g_vpre -> g_vT
// (avg + conv bias, exact fold since bias is spatially constant).
// =====================================================================
template <int MODE>
__global__ void __launch_bounds__(256) pool_kernel(const float* __restrict__ xin,
                                                   const float* __restrict__ bias) {
    extern __shared__ float smemf[];
    float* xs = smemf;              // [3][28][256]
    float* oA = xs + 3 * RR * CC;   // [28][257]
    float* oM = oA + RR * 257;      // [28][257]
    const int bid = blockIdx.x;
    const int b = bid / RR, y = bid % RR;
    const int tid = threadIdx.x;
    const float* src = (MODE == 0) ? xin : g_vpre;

    const int dy0 = (y == 0) ? 0 : -1;
    const int dy1 = (y == RR - 1) ? 0 : 1;
    for (int dy = dy0; dy <= dy1; dy++) {
        const float4* s4 = (const float4*)(src + ((size_t)(b * RR + y + dy) * RR) * CC);
        float4* d4 = (float4*)(xs + (dy + 1) * RR * CC);
        for (int i = tid; i < RR * CC / 4; i += 256) d4[i] = s4[i];
    }
    __syncthreads();

    const int c = tid;
    const int rcnt = dy1 - dy0 + 1;
    for (int px = 0; px < RR; px++) {
        const int x0 = (px > 0) ? px - 1 : 0;
        const int x1 = (px < RR - 1) ? px + 1 : RR - 1;
        float s = 0.f, m = -3.4e38f;
        for (int dy = dy0; dy <= dy1; dy++) {
            const float* row = xs + (dy + 1) * RR * CC;
            for (int xx = x0; xx <= x1; xx++) {
                const float v = row[xx * CC + c];
                s += v;
                if (MODE == 0) m = fmaxf(m, v);
            }
        }
        const float cnt = (float)(rcnt * (x1 - x0 + 1));
        oA[px * 257 + c] = s / cnt;
        if (MODE == 0) oM[px * 257 + c] = m;
    }
    __syncthreads();

    float* dstA = (MODE == 0) ? g_qT : g_vT;
    for (int i = tid; i < RR * CC; i += 256) {
        const int cc = i / RR, px = i % RR;
        const size_t o = ((size_t)(b * CC + cc)) * SS + y * RR + px;
        float v = oA[px * 257 + cc];
        if (MODE == 1) v += __ldg(bias + cc);
        dstA[o] = v;
        if (MODE == 0) g_kT[o] = oM[px * 257 + cc];
    }
}

// =====================================================================
// Kernel 3: per-head QK projection. For (b,h): [64x98] @ [98x128] + bias.
// grid (4 row-tiles, 512 bh, 2 {q,k}); 256 thr; each thread 4x4 f32x2 tile.
// =====================================================================
__global__ void __launch_bounds__(256, 2) proj_kernel(const float* __restrict__ wqk,
                                                      const float* __restrict__ wqkb) {
    extern __shared__ float smemf[];
    float2* Ws = (float2*)smemf;       // [98][64] e-pairs
    float* As = smemf + DR * EE;       // [64][98]
    const int cb = blockIdx.x * 64;
    const int bh = blockIdx.y;
    const int b = bh >> 3, h = bh & 7;
    const int tid = threadIdx.x;
    const float* srcT = blockIdx.z ? g_kT : g_qT;
    float* dst = blockIdx.z ? g_kp : g_qp;

    const float2* wsrc = (const float2*)(wqk + (size_t)h * DR * EE);
    for (int i = tid; i < DR * EE / 2; i += 256) Ws[i] = wsrc[i];
    for (int i = tid; i < 64 * DR; i += 256) {
        const int r = i / DR, d = i - r * DR;
        As[r * DR + d] = srcT[((size_t)(b * CC + cb + r)) * SS + h * DR + d];
    }
    __syncthreads();

    const int tx = tid & 15, ty = tid >> 4;
    u64 acc[4][4];
#pragma unroll
    for (int j = 0; j < 4; j++) {
        const float2 b2 = *(const float2*)(wqkb + h * EE + 2 * (tx + 16 * j));
        const u64 bi = pk2(b2.x, b2.y);
#pragma unroll
        for (int i = 0; i < 4; i++) acc[i][j] = bi;
    }
    for (int k = 0; k < DR; k++) {
        u64 a[4], bw[4];
#pragma unroll
        for (int i = 0; i < 4; i++) { float v = As[(ty + 16 * i) * DR + k]; a[i] = pk2(v, v); }
#pragma unroll
        for (int j = 0; j < 4; j++) bw[j] = *(const u64*)&Ws[k * 64 + tx + 16 * j];
#pragma unroll
        for (int i = 0; i < 4; i++)
#pragma unroll
            for (int j = 0; j < 4; j++) fma2(acc[i][j], a[i], bw[j]);
    }
#pragma unroll
    for (int i = 0; i < 4; i++) {
        float* drow = dst + ((size_t)bh * CC + cb + ty + 16 * i) * EE;
#pragma unroll
        for (int j = 0; j < 4; j++) *(float2*)(drow + 2 * (tx + 16 * j)) = upk(acc[i][j]);
    }
}

// =====================================================================
// Kernel 4: scores = q @ k^T over E=128 (f32x2 over e-pairs, hi+lo fold)
// grid (4 c-tiles, 4 f-tiles, 512 bh); 64x64 out per block.
// =====================================================================
__global__ void __launch_bounds__(256, 3) scores_kernel() {
    extern __shared__ float smemf[];
    float2* qs = (float2*)smemf;     // [64][65]
    float2* ks = qs + 64 * 65;       // [64][65]
    const int cb = blockIdx.x * 64, fb = blockIdx.y * 64;
    const int bh = blockIdx.z;
    const int tid = threadIdx.x;

    const float2* q2 = (const float2*)(g_qp + ((size_t)bh * CC) * EE);
    const float2* k2 = (const float2*)(g_kp + ((size_t)bh * CC) * EE);
    for (int i = tid; i < 64 * 64; i += 256) {
        const int r = i >> 6, e = i & 63;
        qs[r * 65 + e] = q2[(size_t)(cb + r) * 64 + e];
        ks[r * 65 + e] = k2[(size_t)(fb + r) * 64 + e];
    }
    __syncthreads();

    const int tx = tid & 15, ty = tid >> 4;
    u64 acc[4][4];
#pragma unroll
    for (int i = 0; i < 4; i++)
#pragma unroll
        for (int j = 0; j < 4; j++) acc[i][j] = 0ull;

    for (int e = 0; e < 64; e++) {
        u64 a[4], kk[4];
#pragma unroll
        for (int i = 0; i < 4; i++) a[i] = *(const u64*)&qs[(ty + 16 * i) * 65 + e];
#pragma unroll
        for (int j = 0; j < 4; j++) kk[j] = *(const u64*)&ks[(tx + 16 * j) * 65 + e];
#pragma unroll
        for (int i = 0; i < 4; i++)
#pragma unroll
            for (int j = 0; j < 4; j++) fma2(acc[i][j], a[i], kk[j]);
    }
    float* outp = g_scores + ((size_t)bh * CC + cb) * CC + fb;
#pragma unroll
    for (int i = 0; i < 4; i++)
#pragma unroll
        for (int j = 0; j < 4; j++) {
            const float2 v = upk(acc[i][j]);
            outp[(size_t)(ty + 16 * i) * CC + tx + 16 * j] = v.x + v.y;
        }
}

// =====================================================================
// Kernel 5: content temperature. rowmean over f, matvec through wp_w,
// sigmoid, idenom = 128^-(0.2+s) = 2^(-7*(0.2+s)).  One block per bh.
// =====================================================================
__global__ void __launch_bounds__(256) temp_kernel(const float* __restrict__ wp,
                                                   const float* __restrict__ wpb) {
    __shared__ float smean[CC];
    const int bh = blockIdx.x;
    const int tid = threadIdx.x, lane = tid & 31, warp = tid >> 5;

    for (int k = 0; k < 32; k++) {
        const int r = warp + 8 * k;
        const float* row = g_scores + ((size_t)bh * CC + r) * CC;
        float s = 0.f;
#pragma unroll
        for (int j = 0; j < 8; j++) s += row[lane + 32 * j];
#pragma unroll
        for (int o = 16; o; o >>= 1) s += __shfl_xor_sync(0xffffffffu, s, o);
        if (lane == 0) smean[r] = s * (1.f / (float)CC);
    }
    __syncthreads();

    float a = wpb[tid];
    for (int c = 0; c < CC; c++) a = fmaf(smean[c], wp[c * CC + tid], a);
    const float sp = 1.f / (1.f + __expf(-a));
    g_idenom[bh * CC + tid] = exp2f(-7.f * (0.2f + sp));
}

// =====================================================================
// Kernel 6: softmax(scores * idenom) @ v, residual add, write output.
// grid (4 c-tiles, 512 bh); softmax in smem, f32x2 GEMM over f-pairs,
// smem-transposed epilogue for coalesced NHWC stores.
// =====================================================================
__global__ void __launch_bounds__(256, 2) att_kernel(const float* __restrict__ x,
                                                     float* __restrict__ out) {
    extern __shared__ float smemf[];
    float* ss = smemf;              // [64][258] scores tile -> exp values
    float* vsf = ss + 64 * 258;     // [98][66] v chunk; reused as att [64][100]
    __shared__ float rs[64];
    const int cb = blockIdx.x * 64;
    const int bh = blockIdx.y;
    const int b = bh >> 3, h = bh & 7;
    const int tid = threadIdx.x, lane = tid & 31, warp = tid >> 5;

    for (int i = tid; i < 64 * 256; i += 256) {
        const int r = i >> 8, f = i & 255;
        ss[r * 258 + f] = g_scores[((size_t)bh * CC + cb + r) * CC + f];
    }
    __syncthreads();

    // softmax per row (8 warps x 8 rounds = 64 rows), scale by idenom
    for (int k = 0; k < 8; k++) {
        const int r = warp + 8 * k;
        const float id = g_idenom[bh * CC + cb + r];
        float* row = ss + r * 258;
        float m = -3.4e38f;
#pragma unroll
        for (int j = 0; j < 8; j++) m = fmaxf(m, row[lane + 32 * j]);
#pragma unroll
        for (int o = 16; o; o >>= 1) m = fmaxf(m, __shfl_xor_sync(0xffffffffu, m, o));
        float sum = 0.f;
#pragma unroll
        for (int j = 0; j < 8; j++) {
            const float e = __expf((row[lane + 32 * j] - m) * id);
            row[lane + 32 * j] = e;
            sum += e;
        }
#pragma unroll
        for (int o = 16; o; o >>= 1) sum += __shfl_xor_sync(0xffffffffu, sum, o);
        if (lane == 0) rs[r] = 1.f / sum;
    }

    // GEMM: [64 c x 256 f] @ [256 f x 98 d], f chunked by 64
    const int c = tid & 63, dg = tid >> 6;
    u64 acc[25];
#pragma unroll
    for (int k = 0; k < 25; k++) acc[k] = 0ull;

    for (int fc = 0; fc < 4; fc++) {
        __syncthreads();
        for (int i = tid; i < 64 * DR; i += 256) {
            const int f = i / DR, d = i - f * DR;
            vsf[d * 66 + f] = g_vT[((size_t)(b * CC + fc * 64 + f)) * SS + h * DR + d];
        }
        __syncthreads();
        for (int fp = 0; fp < 32; fp++) {
            const u64 sv = *(const u64*)&ss[c * 258 + fc * 64 + 2 * fp];
#pragma unroll
            for (int k = 0; k < 25; k++) {
                const int d = dg + 4 * k;
                if (d < DR) fma2(acc[k], sv, *(const u64*)&vsf[d * 66 + 2 * fp]);
            }
        }
    }

    __syncthreads();
    float* as = vsf; // reuse as att stage [64][100]
#pragma unroll
    for (int k = 0; k < 25; k++) {
        const int d = dg + 4 * k;
        if (d < DR) {
            const float2 v = upk(acc[k]);
            as[c * 100 + d] = (v.x + v.y) * rs[c];
        }
    }
    __syncthreads();

    for (int i = tid; i < DR * 64; i += 256) {
        const int d = i >> 6, cc = i & 63;
        const size_t o = ((size_t)b * SS + h * DR + d) * CC + cb + cc;
        out[o] = x[o] + as[cc * 100 + d];
    }
}

// =====================================================================
extern "C" void kernel_launch(void* const* d_in, const int* in_sizes, int n_in,
                              void* d_out, int out_size) {
    const float* x    = (const float*)d_in[0];
    const float* wqkw = (const float*)d_in[1];
    const float* wqkb = (const float*)d_in[2];
    const float* wpw  = (const float*)d_in[3];
    const float* wpb  = (const float*)d_in[4];
    const float* wvw  = (const float*)d_in[5];
    const float* wvb  = (const float*)d_in[6];
    float* out = (float*)d_out;
    (void)in_sizes; (void)n_in; (void)out_size;

    const int pool_smem  = (3 * RR * CC + 2 * RR * 257) * 4;      // 143584
    const int proj_smem  = (DR * EE + 64 * DR) * 4;               // 75264
    const int sc_smem    = 2 * 64 * 65 * 8;                       // 66560
    const int att_smem   = (64 * 258 + DR * 66) * 4;              // 91920

    cudaFuncSetAttribute(wconv_kernel,   cudaFuncAttributeMaxDynamicSharedMemorySize, WCONV_SMEM);
    cudaFuncSetAttribute(pool_kernel<0>, cudaFuncAttributeMaxDynamicSharedMemorySize, pool_smem);
    cudaFuncSetAttribute(pool_kernel<1>, cudaFuncAttributeMaxDynamicSharedMemorySize, pool_smem);
    cudaFuncSetAttribute(proj_kernel,    cudaFuncAttributeMaxDynamicSharedMemorySize, proj_smem);
    cudaFuncSetAttribute(scores_kernel,  cudaFuncAttributeMaxDynamicSharedMemorySize, sc_smem);
    cudaFuncSetAttribute(att_kernel,     cudaFuncAttributeMaxDynamicSharedMemorySize, att_smem);

    xsplit_kernel<<<(BB * SS * CC + 255) / 256, 256>>>(x);
    wsplit_kernel<<<(36 * 256 * 64 + 255) / 256, 256>>>(wvw);

    dim3 cg(BB * SS / 128, 2);
    wconv_kernel<<<cg, 256, WCONV_SMEM>>>();                  // -> g_vpre (no bias)

    pool_kernel<0><<<BB * RR, 256, pool_smem>>>(x, nullptr);  // x -> g_qT, g_kT
    pool_kernel<1><<<BB * RR, 256, pool_smem>>>(nullptr, wvb);// g_vpre (+bias) -> g_vT

    dim3 pg(4, BB * HH, 2);
    proj_kernel<<<pg, 256, proj_smem>>>(wqkw, wqkb);          // -> g_qp, g_kp

    dim3 sg(4, 4, BB * HH);
    scores_kernel<<<sg, 256, sc_smem>>>();                    // -> g_scores

    temp_kernel<<<BB * HH, 256>>>(wpw, wpb);                  // -> g_idenom

    dim3 ag(4, BB * HH);
    att_kernel<<<ag, 256, att_smem>>>(x, out);                // -> d_out
}